// round 14
// baseline (speedup 1.0000x reference)
#include <cuda_runtime.h>

#define BB 512
#define KK 800
#define DD 512
#define LL 500000
#define NB 24
#define BSZ ((LL + NB - 1) / NB)   // 20834; last bucket slightly smaller

// ---------------------------------------------------------------------------
// Single fused kernel. grid = (x=b fast, y=bucket slow), 256 threads.
// Prologue: stage embed[b] in shared + filter this bucket's items from
// shortlist row b (one int4/thread, warp-aggregated compaction), ONE barrier.
// Main: SPLIT-WARP — each warp processes 2 items at once, 16 lanes per item:
//   * 4-shuffle reduction per item (vs 5) and the two items' load/FMA/shuffle
//     chains interleave in the warp's issue stream -> per-item tail halved
//   * dual accumulators halve the dependent FMA chain
//   * bias gathered up front (hidden under the weight stream)
// Proven invariants kept: 31-reg class / 8 blocks/SM (R4), plain LDG with L1
// allocation (R10), minimal barriers (R9/R11), linear bid order => ~96 MB
// concurrent weight window < L2 => DRAM traffic == unique rows (~573 MB).
// ---------------------------------------------------------------------------
__global__ __launch_bounds__(256, 8) void fused_kernel(
    const float* __restrict__ embed,
    const int*   __restrict__ shortlist,
    const float* __restrict__ sp_weight,
    const float* __restrict__ sp_bias,
    float*       __restrict__ out)
{
    __shared__ float4       s_embed[DD / 4];   // 2 KB
    __shared__ unsigned int s_list[KK];
    __shared__ int          s_cnt;

    const int b      = blockIdx.x;
    const int bucket = blockIdx.y;
    const int t      = threadIdx.x;
    const int lane   = t & 31;

    if (t == 0) s_cnt = 0;
    __syncthreads();

    // ---- overlapped prologue: embed staging + shortlist filter ----
    const float4* erow = reinterpret_cast<const float4*>(embed + (size_t)b * DD);
    if (t < DD / 4)                    // 128 threads, 1 float4 each
        s_embed[t] = erow[t];

    const int lo = bucket * BSZ;
    const int hi = lo + BSZ;           // last bucket: hi > LL harmless (idx < LL)

    const int4* srow = reinterpret_cast<const int4*>(shortlist + (size_t)b * KK);
    int4 v = make_int4(-1, -1, -1, -1);
    if (t < KK / 4)                    // 200 threads, 1 int4 each
        v = srow[t];

    // warp-aggregated compaction, component by component
    #pragma unroll
    for (int c = 0; c < 4; ++c) {
        int idx = (c == 0) ? v.x : (c == 1) ? v.y : (c == 2) ? v.z : v.w;
        bool m = (t < KK / 4) && (idx >= lo) && (idx < hi);
        unsigned bal = __ballot_sync(0xffffffffu, m);
        if (bal) {
            int base = 0;
            if (lane == 0) base = atomicAdd(&s_cnt, __popc(bal));
            base = __shfl_sync(0xffffffffu, base, 0);
            if (m) {
                int off = __popc(bal & ((1u << lane) - 1u));
                int k = t * 4 + c;
                s_list[base + off] = ((unsigned)idx << 10) | (unsigned)k;
            }
        }
    }
    __syncthreads();

    // ---- main: split-warp, 2 items per warp iteration, 16 lanes each ----
    const int cnt  = s_cnt;
    const int warp = t >> 5;
    const int half = lane >> 4;        // 0 = item A, 1 = item B
    const int hl   = lane & 15;        // lane within half-warp

    for (int j2 = warp * 2; j2 < cnt; j2 += 16) {
        const int  jj    = j2 + half;
        const bool valid = (jj < cnt);
        const unsigned int it = s_list[valid ? jj : j2];

        const int       k   = (int)(it & 1023u);
        const long long idx = (long long)(it >> 10);

        // scattered bias gather issued early, hidden under weight loads
        float bias = 0.0f;
        if (hl == 0) bias = __ldg(&sp_bias[idx]);

        const float4* wrow =
            reinterpret_cast<const float4*>(sp_weight + idx * DD);

        float s0 = 0.0f, s1 = 0.0f;
        #pragma unroll
        for (int i = 0; i < 8; i += 2) {   // 8 LDG.128 per half-warp row
            float4 w0 = wrow[i * 16 + hl];
            float4 e0 = s_embed[i * 16 + hl];
            float4 w1 = wrow[(i + 1) * 16 + hl];
            float4 e1 = s_embed[(i + 1) * 16 + hl];
            s0 = fmaf(w0.x, e0.x, s0); s0 = fmaf(w0.y, e0.y, s0);
            s0 = fmaf(w0.z, e0.z, s0); s0 = fmaf(w0.w, e0.w, s0);
            s1 = fmaf(w1.x, e1.x, s1); s1 = fmaf(w1.y, e1.y, s1);
            s1 = fmaf(w1.z, e1.z, s1); s1 = fmaf(w1.w, e1.w, s1);
        }
        float sum = s0 + s1;

        // 16-lane butterfly reduction (stays within each half-warp)
        #pragma unroll
        for (int off = 8; off; off >>= 1)
            sum += __shfl_xor_sync(0xffffffffu, sum, off);

        if (hl == 0 && valid)
            out[b * KK + k] = sum + bias;
    }
}

extern "C" void kernel_launch(void* const* d_in, const int* in_sizes, int n_in,
                              void* d_out, int out_size) {
    const float* embed     = (const float*)d_in[0];
    const int*   shortlist = (const int*)  d_in[1];
    const float* sp_weight = (const float*)d_in[2];
    const float* sp_bias   = (const float*)d_in[3];
    float*       out       = (float*)d_out;

    fused_kernel<<<dim3(BB, NB), 256>>>(embed, shortlist, sp_weight, sp_bias, out);
}

// round 15
// speedup vs baseline: 1.0475x; 1.0475x over previous
#include <cuda_runtime.h>

#define BB 512
#define KK 800
#define DD 512
#define LL 500000
#define NB 24
#define BSZ ((LL + NB - 1) / NB)   // 20834; last bucket slightly smaller

// ---------------------------------------------------------------------------
// Single fused kernel. grid = (x=b fast, y=bucket slow), 256 threads.
// Per block (b,bucket): stage embed[b] in shared + filter this bucket's items
// out of shortlist row b (one int4 per thread, warp-aggregated compaction),
// ONE barrier, then warp-per-item float4 dot products.
//
// Proven invariants (12+ rounds of evidence):
//  * linear bid order => ~96 MB concurrent weight window < L2 => duplicate
//    rows across b are L2 hits; DRAM traffic == unique rows (~573 MB floor)
//  * 31/32-reg class, 8 blocks/SM (R4: deeper per-warp MLP kills occupancy)
//  * plain LDG.128 w/ L1 allocation (R10: __ldcg costs 1.15 TB/s)
//  * minimal barriers (R9 persistent / R11 sort: barrier coupling costs 10us+)
//  * FULL warp per row: one 512B wavefront per LDG (R14: split-warp doubles
//    wavefronts and costs 0.6 TB/s)
//  * bias gather hoisted ahead of the weight loop (R13: -3 us tail latency)
//  * dual accumulators: dependent FMA chain 16 -> 8+1 (this round)
// ---------------------------------------------------------------------------
__global__ __launch_bounds__(256, 8) void fused_kernel(
    const float* __restrict__ embed,
    const int*   __restrict__ shortlist,
    const float* __restrict__ sp_weight,
    const float* __restrict__ sp_bias,
    float*       __restrict__ out)
{
    __shared__ float4       s_embed[DD / 4];   // 2 KB
    __shared__ unsigned int s_list[KK];
    __shared__ int          s_cnt;

    const int b      = blockIdx.x;
    const int bucket = blockIdx.y;
    const int t      = threadIdx.x;
    const int lane   = t & 31;

    if (t == 0) s_cnt = 0;
    __syncthreads();

    // ---- overlapped prologue: embed staging + shortlist filter ----
    const float4* erow = reinterpret_cast<const float4*>(embed + (size_t)b * DD);
    if (t < DD / 4)                    // 128 threads, 1 float4 each
        s_embed[t] = erow[t];

    const int lo = bucket * BSZ;
    const int hi = lo + BSZ;           // last bucket: hi > LL harmless (idx < LL)

    const int4* srow = reinterpret_cast<const int4*>(shortlist + (size_t)b * KK);
    int4 v = make_int4(-1, -1, -1, -1);
    if (t < KK / 4)                    // 200 threads, 1 int4 each
        v = srow[t];

    // warp-aggregated compaction, component by component
    #pragma unroll
    for (int c = 0; c < 4; ++c) {
        int idx = (c == 0) ? v.x : (c == 1) ? v.y : (c == 2) ? v.z : v.w;
        bool m = (t < KK / 4) && (idx >= lo) && (idx < hi);
        unsigned bal = __ballot_sync(0xffffffffu, m);
        if (bal) {
            int base = 0;
            if (lane == 0) base = atomicAdd(&s_cnt, __popc(bal));
            base = __shfl_sync(0xffffffffu, base, 0);
            if (m) {
                int off = __popc(bal & ((1u << lane) - 1u));
                int k = t * 4 + c;
                s_list[base + off] = ((unsigned)idx << 10) | (unsigned)k;
            }
        }
    }
    __syncthreads();

    // ---- main: warp per item, float4-coalesced weight-row dot ----
    const int cnt  = s_cnt;
    const int warp = t >> 5;

    for (int j = warp; j < cnt; j += 8) {
        const unsigned int it  = s_list[j];
        const int          k   = (int)(it & 1023u);
        const long long    idx = (long long)(it >> 10);

        // scattered bias gather issued early; consumed after the reduction
        float bias = 0.0f;
        if (lane == 0) bias = __ldg(&sp_bias[idx]);

        const float4* wrow =
            reinterpret_cast<const float4*>(sp_weight + idx * DD);

        float s0 = 0.0f, s1 = 0.0f;    // dual accumulators: FMA chain 16 -> 8
        #pragma unroll
        for (int i = 0; i < DD / 128; i += 2) {   // 4 independent LDG.128
            float4 w0 = wrow[i * 32 + lane];
            float4 e0 = s_embed[i * 32 + lane];
            float4 w1 = wrow[(i + 1) * 32 + lane];
            float4 e1 = s_embed[(i + 1) * 32 + lane];
            s0 = fmaf(w0.x, e0.x, s0); s0 = fmaf(w0.y, e0.y, s0);
            s0 = fmaf(w0.z, e0.z, s0); s0 = fmaf(w0.w, e0.w, s0);
            s1 = fmaf(w1.x, e1.x, s1); s1 = fmaf(w1.y, e1.y, s1);
            s1 = fmaf(w1.z, e1.z, s1); s1 = fmaf(w1.w, e1.w, s1);
        }
        float sum = s0 + s1;

        #pragma unroll
        for (int off = 16; off; off >>= 1)
            sum += __shfl_xor_sync(0xffffffffu, sum, off);

        if (lane == 0)
            out[b * KK + k] = sum + bias;
    }
}

extern "C" void kernel_launch(void* const* d_in, const int* in_sizes, int n_in,
                              void* d_out, int out_size) {
    const float* embed     = (const float*)d_in[0];
    const int*   shortlist = (const int*)  d_in[1];
    const float* sp_weight = (const float*)d_in[2];
    const float* sp_bias   = (const float*)d_in[3];
    float*       out       = (float*)d_out;

    fused_kernel<<<dim3(BB, NB), 256>>>(embed, shortlist, sp_weight, sp_bias, out);
}

// round 16
// speedup vs baseline: 1.0696x; 1.0211x over previous
#include <cuda_runtime.h>

#define BB 512
#define KK 800
#define DD 512
#define LL 500000
#define NB 24
#define BSZ ((LL + NB - 1) / NB)   // 20834; last bucket slightly smaller

// ---------------------------------------------------------------------------
// Single fused kernel. grid = (x=b fast, y=bucket slow), 256 threads.
// Per block (b,bucket): stage embed[b] in shared + filter this bucket's items
// out of shortlist row b (one int4 per thread, warp-aggregated compaction),
// ONE barrier, then warp-per-item float4 dot products.
//
// Proven invariants (15 rounds of evidence — do not perturb):
//  * linear bid order => ~96 MB concurrent weight window < L2 => duplicate
//    rows across b are L2 hits; DRAM traffic == unique rows (~573 MB floor)
//  * 31-reg class, 8 blocks/SM (R4: deeper per-warp MLP kills occupancy)
//  * plain LDG.128 w/ L1 allocation (R10: __ldcg costs 1.15 TB/s)
//  * minimal barriers (R9 persistent / R11 sort: barrier coupling costs 10us+)
//  * FULL warp per row: one 512B wavefront per LDG (R14: split-warp -0.6TB/s)
//  * simple loop body so ptxas front-batches all 4 LDGs (R15: manual
//    pairing/interleaving breaks the load schedule, -0.3 TB/s)
//  * bias gather hoisted ahead of the weight loop (R13: -3 us tail latency)
// ---------------------------------------------------------------------------
__global__ __launch_bounds__(256, 8) void fused_kernel(
    const float* __restrict__ embed,
    const int*   __restrict__ shortlist,
    const float* __restrict__ sp_weight,
    const float* __restrict__ sp_bias,
    float*       __restrict__ out)
{
    __shared__ float4       s_embed[DD / 4];   // 2 KB
    __shared__ unsigned int s_list[KK];
    __shared__ int          s_cnt;

    const int b      = blockIdx.x;
    const int bucket = blockIdx.y;
    const int t      = threadIdx.x;
    const int lane   = t & 31;

    if (t == 0) s_cnt = 0;
    __syncthreads();

    // ---- overlapped prologue: embed staging + shortlist filter ----
    const float4* erow = reinterpret_cast<const float4*>(embed + (size_t)b * DD);
    if (t < DD / 4)                    // 128 threads, 1 float4 each
        s_embed[t] = erow[t];

    const int lo = bucket * BSZ;
    const int hi = lo + BSZ;           // last bucket: hi > LL harmless (idx < LL)

    const int4* srow = reinterpret_cast<const int4*>(shortlist + (size_t)b * KK);
    int4 v = make_int4(-1, -1, -1, -1);
    if (t < KK / 4)                    // 200 threads, 1 int4 each
        v = srow[t];

    // warp-aggregated compaction, component by component
    #pragma unroll
    for (int c = 0; c < 4; ++c) {
        int idx = (c == 0) ? v.x : (c == 1) ? v.y : (c == 2) ? v.z : v.w;
        bool m = (t < KK / 4) && (idx >= lo) && (idx < hi);
        unsigned bal = __ballot_sync(0xffffffffu, m);
        if (bal) {
            int base = 0;
            if (lane == 0) base = atomicAdd(&s_cnt, __popc(bal));
            base = __shfl_sync(0xffffffffu, base, 0);
            if (m) {
                int off = __popc(bal & ((1u << lane) - 1u));
                int k = t * 4 + c;
                s_list[base + off] = ((unsigned)idx << 10) | (unsigned)k;
            }
        }
    }
    __syncthreads();

    // ---- main: warp per item, float4-coalesced weight-row dot ----
    const int cnt  = s_cnt;
    const int warp = t >> 5;

    for (int j = warp; j < cnt; j += 8) {
        const unsigned int it  = s_list[j];
        const int          k   = (int)(it & 1023u);
        const long long    idx = (long long)(it >> 10);

        // issue the scattered bias gather early; consumed after the reduction
        float bias = 0.0f;
        if (lane == 0) bias = __ldg(&sp_bias[idx]);

        const float4* wrow =
            reinterpret_cast<const float4*>(sp_weight + idx * DD);

        float sum = 0.0f;
        #pragma unroll
        for (int i = 0; i < DD / 128; ++i) {   // 4 independent LDG.128
            float4 w = wrow[i * 32 + lane];
            float4 e = s_embed[i * 32 + lane];
            sum = fmaf(w.x, e.x, sum);
            sum = fmaf(w.y, e.y, sum);
            sum = fmaf(w.z, e.z, sum);
            sum = fmaf(w.w, e.w, sum);
        }

        #pragma unroll
        for (int off = 16; off; off >>= 1)
            sum += __shfl_xor_sync(0xffffffffu, sum, off);

        if (lane == 0)
            out[b * KK + k] = sum + bias;
    }
}

extern "C" void kernel_launch(void* const* d_in, const int* in_sizes, int n_in,
                              void* d_out, int out_size) {
    const float* embed     = (const float*)d_in[0];
    const int*   shortlist = (const int*)  d_in[1];
    const float* sp_weight = (const float*)d_in[2];
    const float* sp_bias   = (const float*)d_in[3];
    float*       out       = (float*)d_out;

    fused_kernel<<<dim3(BB, NB), 256>>>(embed, shortlist, sp_weight, sp_bias, out);
}

// round 17
// speedup vs baseline: 1.0708x; 1.0010x over previous
#include <cuda_runtime.h>

#define BB 512
#define KK 800
#define DD 512
#define LL 500000
#define NB 22
#define BSZ ((LL + NB - 1) / NB)   // 22728; last bucket slightly smaller

// ---------------------------------------------------------------------------
// Single fused kernel. grid = (x=b fast, y=bucket slow), 256 threads.
// Per block (b,bucket): stage embed[b] in shared + filter this bucket's items
// out of shortlist row b (one int4 per thread, warp-aggregated compaction),
// ONE barrier, then warp-per-item float4 dot products.
//
// Proven invariants (16 rounds of evidence — do not perturb):
//  * linear bid order => ~105 MB concurrent weight window < L2 => duplicate
//    rows across b are L2 hits; DRAM traffic == unique rows (~573 MB floor)
//  * 31-reg class, 8 blocks/SM (R4: deeper per-warp MLP kills occupancy)
//  * plain LDG.128 w/ L1 allocation (R10: __ldcg costs 1.15 TB/s)
//  * minimal barriers (R9 persistent / R11 sort: barrier coupling costs 10us+)
//  * FULL warp per row: one 512B wavefront per LDG (R14: split-warp -0.6TB/s)
//  * simple loop body so ptxas front-batches all 4 LDGs (R15: manual
//    pairing/interleaving breaks the load schedule, -0.3 TB/s)
//  * bias gather hoisted ahead of the weight loop (R13: -3 us tail latency)
//  * NB=22 (this round): -8% cells => less prologue overhead; window margin
//    kept ~15 MB (NB=20's 115 MB window risks duplicate-spill to DRAM)
// ---------------------------------------------------------------------------
__global__ __launch_bounds__(256, 8) void fused_kernel(
    const float* __restrict__ embed,
    const int*   __restrict__ shortlist,
    const float* __restrict__ sp_weight,
    const float* __restrict__ sp_bias,
    float*       __restrict__ out)
{
    __shared__ float4       s_embed[DD / 4];   // 2 KB
    __shared__ unsigned int s_list[KK];
    __shared__ int          s_cnt;

    const int b      = blockIdx.x;
    const int bucket = blockIdx.y;
    const int t      = threadIdx.x;
    const int lane   = t & 31;

    if (t == 0) s_cnt = 0;
    __syncthreads();

    // ---- overlapped prologue: embed staging + shortlist filter ----
    const float4* erow = reinterpret_cast<const float4*>(embed + (size_t)b * DD);
    if (t < DD / 4)                    // 128 threads, 1 float4 each
        s_embed[t] = erow[t];

    const int lo = bucket * BSZ;
    const int hi = lo + BSZ;           // last bucket: hi > LL harmless (idx < LL)

    const int4* srow = reinterpret_cast<const int4*>(shortlist + (size_t)b * KK);
    int4 v = make_int4(-1, -1, -1, -1);
    if (t < KK / 4)                    // 200 threads, 1 int4 each
        v = srow[t];

    // warp-aggregated compaction, component by component
    #pragma unroll
    for (int c = 0; c < 4; ++c) {
        int idx = (c == 0) ? v.x : (c == 1) ? v.y : (c == 2) ? v.z : v.w;
        bool m = (t < KK / 4) && (idx >= lo) && (idx < hi);
        unsigned bal = __ballot_sync(0xffffffffu, m);
        if (bal) {
            int base = 0;
            if (lane == 0) base = atomicAdd(&s_cnt, __popc(bal));
            base = __shfl_sync(0xffffffffu, base, 0);
            if (m) {
                int off = __popc(bal & ((1u << lane) - 1u));
                int k = t * 4 + c;
                s_list[base + off] = ((unsigned)idx << 10) | (unsigned)k;
            }
        }
    }
    __syncthreads();

    // ---- main: warp per item, float4-coalesced weight-row dot ----
    const int cnt  = s_cnt;
    const int warp = t >> 5;

    for (int j = warp; j < cnt; j += 8) {
        const unsigned int it  = s_list[j];
        const int          k   = (int)(it & 1023u);
        const long long    idx = (long long)(it >> 10);

        // issue the scattered bias gather early; consumed after the reduction
        float bias = 0.0f;
        if (lane == 0) bias = __ldg(&sp_bias[idx]);

        const float4* wrow =
            reinterpret_cast<const float4*>(sp_weight + idx * DD);

        float sum = 0.0f;
        #pragma unroll
        for (int i = 0; i < DD / 128; ++i) {   // 4 independent LDG.128
            float4 w = wrow[i * 32 + lane];
            float4 e = s_embed[i * 32 + lane];
            sum = fmaf(w.x, e.x, sum);
            sum = fmaf(w.y, e.y, sum);
            sum = fmaf(w.z, e.z, sum);
            sum = fmaf(w.w, e.w, sum);
        }

        #pragma unroll
        for (int off = 16; off; off >>= 1)
            sum += __shfl_xor_sync(0xffffffffu, sum, off);

        if (lane == 0)
            out[b * KK + k] = sum + bias;
    }
}

extern "C" void kernel_launch(void* const* d_in, const int* in_sizes, int n_in,
                              void* d_out, int out_size) {
    const float* embed     = (const float*)d_in[0];
    const int*   shortlist = (const int*)  d_in[1];
    const float* sp_weight = (const float*)d_in[2];
    const float* sp_bias   = (const float*)d_in[3];
    float*       out       = (float*)d_out;

    fused_kernel<<<dim3(BB, NB), 256>>>(embed, shortlist, sp_weight, sp_bias, out);
}